// round 1
// baseline (speedup 1.0000x reference)
#include <cuda_runtime.h>
#include <cstdint>

#define NPTS  4096
#define BATCH 8
#define KNN_K 16

// scratch for neighbor indices (within-batch indices), 8*4096*16 ints = 2MB
__device__ int g_idx[BATCH * NPTS * KNN_K];

// ---------------------------------------------------------------------------
// packed f32x2 helpers
// ---------------------------------------------------------------------------
__device__ __forceinline__ unsigned long long ffma2(unsigned long long a,
                                                    unsigned long long b,
                                                    unsigned long long c) {
    unsigned long long d;
    asm("fma.rn.f32x2 %0, %1, %2, %3;" : "=l"(d) : "l"(a), "l"(b), "l"(c));
    return d;
}
__device__ __forceinline__ unsigned long long pack2(float lo, float hi) {
    unsigned long long p;
    asm("mov.b64 %0, {%1, %2};" : "=l"(p) : "f"(lo), "f"(hi));
    return p;
}
__device__ __forceinline__ void unpack2(unsigned long long p, float& lo, float& hi) {
    asm("mov.b64 {%0, %1}, %2;" : "=f"(lo), "=f"(hi) : "l"(p));
}

// ---------------------------------------------------------------------------
// Kernel 1: brute-force exact KNN (top-16 by dist = sq[n]+sq[m]-2*dot, ties by idx)
// ---------------------------------------------------------------------------
extern "C" __global__ void __launch_bounds__(128)
knn_kernel(const float* __restrict__ x) {
    extern __shared__ __align__(16) char smem_raw[];
    float4* pts = (float4*)smem_raw;   // x, y, sq, pad : 64KB

    const int tid = threadIdx.x;
    const int b   = blockIdx.y;
    const float2* __restrict__ xb = ((const float2*)x) + (size_t)b * NPTS;

    for (int i = tid; i < NPTS; i += 128) {
        float2 v = xb[i];
        float sq = __fadd_rn(__fmul_rn(v.x, v.x), __fmul_rn(v.y, v.y));
        pts[i] = make_float4(v.x, v.y, sq, 0.0f);
    }
    __syncthreads();

    const int q = blockIdx.x * 128 + tid;
    const float4 qp = pts[q];
    const float qx = qp.x, qy = qp.y, qsq = qp.z;

    // sorted top-16: bu ascending (monotone-mapped distance bits), bi = index
    unsigned bu[KNN_K];
    int      bi[KNN_K];
#pragma unroll
    for (int s = 0; s < KNN_K; ++s) { bu[s] = 0xFFFFFFFFu; bi[s] = 0; }

#pragma unroll 4
    for (int j = 0; j < NPTS; ++j) {
        float4 p = pts[j];
        // exact reference formula, no FMA contraction
        float dot = __fadd_rn(__fmul_rn(qx, p.x), __fmul_rn(qy, p.y));
        float d   = __fsub_rn(__fadd_rn(qsq, p.z), __fmul_rn(2.0f, dot));
        int ib = __float_as_int(d);
        unsigned u = (ib >= 0) ? ((unsigned)ib ^ 0x80000000u) : ~(unsigned)ib;
        if (u < bu[KNN_K - 1]) {
            bool c[KNN_K];
#pragma unroll
            for (int s = 0; s < KNN_K; ++s) c[s] = (u < bu[s]);
#pragma unroll
            for (int s = KNN_K - 1; s >= 1; --s) {
                bu[s] = c[s - 1] ? bu[s - 1] : (c[s] ? u : bu[s]);
                bi[s] = c[s - 1] ? bi[s - 1] : (c[s] ? j : bi[s]);
            }
            if (c[0]) { bu[0] = u; bi[0] = j; }
        }
    }

    int* out = g_idx + ((size_t)b * NPTS + q) * KNN_K;
#pragma unroll
    for (int s = 0; s < KNN_K; ++s) out[s] = bi[s];
}

// ---------------------------------------------------------------------------
// Kernel 2: fused MLP chain + pooling + final layer + L2 normalize
// ---------------------------------------------------------------------------
struct __align__(16) SmemMLP {
    float2 pts[NPTS];          // 32KB
    float w1[32];              // [8][4]
    float w2[64];              // [8][8]
    float w3[128];             // [16][8]
    float w4[1024];            // [64][16]
    float w5[9216];            // [96][96]
    float mw[64];              // [4][16]
    float mb[4];
    float s1[8],  b1[8];
    float s2[8],  b2[8];
    float s3[16], b3[16];
    float s4[64], b4[64];
    float s5[96], b5[96];
};

extern "C" __global__ void __launch_bounds__(128)
mlp_kernel(const float* __restrict__ x,
           const float* __restrict__ w1, const float* __restrict__ w2,
           const float* __restrict__ w3, const float* __restrict__ w4,
           const float* __restrict__ w5,
           const float* __restrict__ mw, const float* __restrict__ mb,
           const float* __restrict__ bn1, const float* __restrict__ bn2,
           const float* __restrict__ bn3, const float* __restrict__ bn4,
           const float* __restrict__ bn5,
           float* __restrict__ out) {
    extern __shared__ __align__(16) char smem_raw[];
    SmemMLP* sm = (SmemMLP*)smem_raw;

    const int tid = threadIdx.x;
    const int b   = blockIdx.y;

    // cooperative loads
    for (int i = tid; i < NPTS; i += 128) sm->pts[i] = ((const float2*)x)[(size_t)b * NPTS + i];
    for (int i = tid; i < 32;   i += 128) sm->w1[i] = w1[i];
    for (int i = tid; i < 64;   i += 128) sm->w2[i] = w2[i];
    for (int i = tid; i < 128;  i += 128) sm->w3[i] = w3[i];
    for (int i = tid; i < 1024; i += 128) sm->w4[i] = w4[i];
    for (int i = tid; i < 9216; i += 128) sm->w5[i] = w5[i];
    for (int i = tid; i < 64;   i += 128) sm->mw[i] = mw[i];
    if (tid < 4) sm->mb[tid] = mb[tid];
    // fold BN: scale = gamma*rsqrt(var+eps); bias = beta - mean*scale
    for (int i = tid; i < 8;  i += 128) {
        float s = bn1[i] * rsqrtf(bn1[24 + i] + 1e-5f);
        sm->s1[i] = s; sm->b1[i] = bn1[8 + i] - bn1[16 + i] * s;
        float t = bn2[i] * rsqrtf(bn2[24 + i] + 1e-5f);
        sm->s2[i] = t; sm->b2[i] = bn2[8 + i] - bn2[16 + i] * t;
    }
    for (int i = tid; i < 16; i += 128) {
        float s = bn3[i] * rsqrtf(bn3[48 + i] + 1e-5f);
        sm->s3[i] = s; sm->b3[i] = bn3[16 + i] - bn3[32 + i] * s;
    }
    for (int i = tid; i < 64; i += 128) {
        float s = bn4[i] * rsqrtf(bn4[192 + i] + 1e-5f);
        sm->s4[i] = s; sm->b4[i] = bn4[64 + i] - bn4[128 + i] * s;
    }
    for (int i = tid; i < 96; i += 128) {
        float s = bn5[i] * rsqrtf(bn5[288 + i] + 1e-5f);
        sm->s5[i] = s; sm->b5[i] = bn5[96 + i] - bn5[192 + i] * s;
    }
    __syncthreads();

    const int n  = blockIdx.x * 128 + tid;
    const int gq = b * NPTS + n;
    const int* __restrict__ gi = g_idx + (size_t)gq * KNN_K;

    float f[96];
#pragma unroll
    for (int i = 0; i < 96; ++i) f[i] = 0.0f;

    const float2 ctr = sm->pts[n];

#pragma unroll 1
    for (int k = 0; k < KNN_K; ++k) {
        const int nbk = gi[k];
        const float2 P = sm->pts[nbk];
        const float m1 = sm->mw[k];
        const float m2 = sm->mw[16 + k];
        const float m3 = sm->mw[32 + k];
        const float m4 = sm->mw[48 + k];

        // layer 1: 4 -> 8
        float h1[8];
#pragma unroll
        for (int o = 0; o < 8; ++o) {
            float4 w = *(const float4*)(sm->w1 + o * 4);
            float v = P.x * w.x + P.y * w.y + ctr.x * w.z + ctr.y * w.w;
            v = fmaxf(fmaf(v, sm->s1[o], sm->b1[o]), 0.0f);
            h1[o] = v;
            f[o] = fmaf(v, m1, f[o]);
        }
        // layer 2: 8 -> 8
        float h2[8];
#pragma unroll
        for (int o = 0; o < 8; ++o) {
            const float4* w = (const float4*)(sm->w2 + o * 8);
            float4 wa = w[0], wb = w[1];
            float v = h1[0] * wa.x + h1[1] * wa.y + h1[2] * wa.z + h1[3] * wa.w
                    + h1[4] * wb.x + h1[5] * wb.y + h1[6] * wb.z + h1[7] * wb.w;
            v = fmaxf(fmaf(v, sm->s2[o], sm->b2[o]), 0.0f);
            h2[o] = v;
            f[8 + o] = fmaf(v, m2, f[8 + o]);
        }
        // layer 3: 8 -> 16, stored packed in pairs for layer-4 f32x2 dots
        unsigned long long h3p[8];
#pragma unroll
        for (int o = 0; o < 16; o += 2) {
            float vv[2];
#pragma unroll
            for (int t = 0; t < 2; ++t) {
                const float4* w = (const float4*)(sm->w3 + (o + t) * 8);
                float4 wa = w[0], wb = w[1];
                float v = h2[0] * wa.x + h2[1] * wa.y + h2[2] * wa.z + h2[3] * wa.w
                        + h2[4] * wb.x + h2[5] * wb.y + h2[6] * wb.z + h2[7] * wb.w;
                v = fmaxf(fmaf(v, sm->s3[o + t], sm->b3[o + t]), 0.0f);
                f[16 + o + t] = fmaf(v, m3, f[16 + o + t]);
                vv[t] = v;
            }
            h3p[o / 2] = pack2(vv[0], vv[1]);
        }
        // layer 4: 16 -> 64 (packed f32x2 dot16)
#pragma unroll
        for (int o = 0; o < 64; ++o) {
            const ulonglong2* wrow = (const ulonglong2*)(sm->w4 + o * 16);
            ulonglong2 wa = wrow[0], wb = wrow[1], wc = wrow[2], wd = wrow[3];
            unsigned long long acc = ffma2(h3p[0], wa.x, 0ULL);
            acc = ffma2(h3p[1], wa.y, acc);
            acc = ffma2(h3p[2], wb.x, acc);
            acc = ffma2(h3p[3], wb.y, acc);
            acc = ffma2(h3p[4], wc.x, acc);
            acc = ffma2(h3p[5], wc.y, acc);
            acc = ffma2(h3p[6], wd.x, acc);
            acc = ffma2(h3p[7], wd.y, acc);
            float lo, hi; unpack2(acc, lo, hi);
            float v = lo + hi;
            v = fmaxf(fmaf(v, sm->s4[o], sm->b4[o]), 0.0f);
            f[32 + o] = fmaf(v, m4, f[32 + o]);
        }
    }

    // mlp biases (per segment scalar)
    {
        const float c0 = sm->mb[0], c1 = sm->mb[1], c2 = sm->mb[2], c3 = sm->mb[3];
#pragma unroll
        for (int o = 0; o < 8; ++o)  f[o]      += c0;
#pragma unroll
        for (int o = 0; o < 8; ++o)  f[8 + o]  += c1;
#pragma unroll
        for (int o = 0; o < 16; ++o) f[16 + o] += c2;
#pragma unroll
        for (int o = 0; o < 64; ++o) f[32 + o] += c3;
    }

    // pack f for packed final-layer dots
    unsigned long long fp[48];
#pragma unroll
    for (int i = 0; i < 48; ++i) fp[i] = pack2(f[2 * i], f[2 * i + 1]);

    float* __restrict__ outp = out + (size_t)gq * 96;
    float ss = 0.0f;
#pragma unroll 2
    for (int o = 0; o < 96; ++o) {
        const ulonglong2* w = (const ulonglong2*)(sm->w5 + o * 96);
        unsigned long long acc = 0ULL;
#pragma unroll
        for (int j = 0; j < 24; ++j) {
            ulonglong2 ww = w[j];
            acc = ffma2(fp[2 * j],     ww.x, acc);
            acc = ffma2(fp[2 * j + 1], ww.y, acc);
        }
        float lo, hi; unpack2(acc, lo, hi);
        float v = lo + hi;
        v = fmaxf(fmaf(v, sm->s5[o], sm->b5[o]), 0.0f);
        ss = fmaf(v, v, ss);
        outp[o] = v;
    }

    const float rn = rsqrtf(ss);
    float4* o4 = (float4*)outp;
#pragma unroll 4
    for (int i = 0; i < 24; ++i) {
        float4 v = o4[i];
        v.x *= rn; v.y *= rn; v.z *= rn; v.w *= rn;
        o4[i] = v;
    }
}

// ---------------------------------------------------------------------------
// launch
// ---------------------------------------------------------------------------
extern "C" void kernel_launch(void* const* d_in, const int* in_sizes, int n_in,
                              void* d_out, int out_size) {
    const float* x   = (const float*)d_in[0];
    const float* w1  = (const float*)d_in[1];
    const float* w2  = (const float*)d_in[2];
    const float* w3  = (const float*)d_in[3];
    const float* w4  = (const float*)d_in[4];
    const float* w5  = (const float*)d_in[5];
    const float* mw  = (const float*)d_in[6];
    const float* mb  = (const float*)d_in[7];
    const float* bn1 = (const float*)d_in[8];
    const float* bn2 = (const float*)d_in[9];
    const float* bn3 = (const float*)d_in[10];
    const float* bn4 = (const float*)d_in[11];
    const float* bn5 = (const float*)d_in[12];

    const size_t knn_smem = NPTS * sizeof(float4);   // 64KB
    const size_t mlp_smem = sizeof(SmemMLP);         // ~75KB

    cudaFuncSetAttribute(knn_kernel, cudaFuncAttributeMaxDynamicSharedMemorySize, (int)knn_smem);
    cudaFuncSetAttribute(mlp_kernel, cudaFuncAttributeMaxDynamicSharedMemorySize, (int)mlp_smem);

    dim3 grid(NPTS / 128, BATCH);
    knn_kernel<<<grid, 128, knn_smem>>>(x);
    mlp_kernel<<<grid, 128, mlp_smem>>>(x, w1, w2, w3, w4, w5, mw, mb,
                                        bn1, bn2, bn3, bn4, bn5, (float*)d_out);
}

// round 2
// speedup vs baseline: 2.8539x; 2.8539x over previous
#include <cuda_runtime.h>
#include <cstdint>

#define NPTS  4096
#define BATCH 8
#define KNN_K 16

// scratch for neighbor indices (within-batch indices), 8*4096*16 ints = 2MB
__device__ int g_idx[BATCH * NPTS * KNN_K];

// ---------------------------------------------------------------------------
// packed f32x2 helpers
// ---------------------------------------------------------------------------
__device__ __forceinline__ unsigned long long ffma2(unsigned long long a,
                                                    unsigned long long b,
                                                    unsigned long long c) {
    unsigned long long d;
    asm("fma.rn.f32x2 %0, %1, %2, %3;" : "=l"(d) : "l"(a), "l"(b), "l"(c));
    return d;
}
__device__ __forceinline__ unsigned long long add2(unsigned long long a,
                                                   unsigned long long b) {
    unsigned long long d;
    asm("add.rn.f32x2 %0, %1, %2;" : "=l"(d) : "l"(a), "l"(b));
    return d;
}
__device__ __forceinline__ unsigned long long pack2(float lo, float hi) {
    unsigned long long p;
    asm("mov.b64 %0, {%1, %2};" : "=l"(p) : "f"(lo), "f"(hi));
    return p;
}
__device__ __forceinline__ void unpack2(unsigned long long p, float& lo, float& hi) {
    asm("mov.b64 {%0, %1}, %2;" : "=f"(lo), "=f"(hi) : "l"(p));
}

// ---------------------------------------------------------------------------
// Kernel 1: brute-force exact KNN (top-16 by dist = sq[n]+sq[m]-2*dot, ties by idx)
// (unchanged from round 1 — measured ~issue-bound, ~370us; round-3 target)
// ---------------------------------------------------------------------------
extern "C" __global__ void __launch_bounds__(128)
knn_kernel(const float* __restrict__ x) {
    extern __shared__ __align__(16) char smem_raw[];
    float4* pts = (float4*)smem_raw;   // x, y, sq, pad : 64KB

    const int tid = threadIdx.x;
    const int b   = blockIdx.y;
    const float2* __restrict__ xb = ((const float2*)x) + (size_t)b * NPTS;

    for (int i = tid; i < NPTS; i += 128) {
        float2 v = xb[i];
        float sq = __fadd_rn(__fmul_rn(v.x, v.x), __fmul_rn(v.y, v.y));
        pts[i] = make_float4(v.x, v.y, sq, 0.0f);
    }
    __syncthreads();

    const int q = blockIdx.x * 128 + tid;
    const float4 qp = pts[q];
    const float qx = qp.x, qy = qp.y, qsq = qp.z;

    // sorted top-16: bu ascending (monotone-mapped distance bits), bi = index
    unsigned bu[KNN_K];
    int      bi[KNN_K];
#pragma unroll
    for (int s = 0; s < KNN_K; ++s) { bu[s] = 0xFFFFFFFFu; bi[s] = 0; }

#pragma unroll 4
    for (int j = 0; j < NPTS; ++j) {
        float4 p = pts[j];
        // exact reference formula, no FMA contraction
        float dot = __fadd_rn(__fmul_rn(qx, p.x), __fmul_rn(qy, p.y));
        float d   = __fsub_rn(__fadd_rn(qsq, p.z), __fmul_rn(2.0f, dot));
        int ib = __float_as_int(d);
        unsigned u = (ib >= 0) ? ((unsigned)ib ^ 0x80000000u) : ~(unsigned)ib;
        if (u < bu[KNN_K - 1]) {
            bool c[KNN_K];
#pragma unroll
            for (int s = 0; s < KNN_K; ++s) c[s] = (u < bu[s]);
#pragma unroll
            for (int s = KNN_K - 1; s >= 1; --s) {
                bu[s] = c[s - 1] ? bu[s - 1] : (c[s] ? u : bu[s]);
                bi[s] = c[s - 1] ? bi[s - 1] : (c[s] ? j : bi[s]);
            }
            if (c[0]) { bu[0] = u; bi[0] = j; }
        }
    }

    int* out = g_idx + ((size_t)b * NPTS + q) * KNN_K;
#pragma unroll
    for (int s = 0; s < KNN_K; ++s) out[s] = bi[s];
}

// ---------------------------------------------------------------------------
// Kernel 2: fused MLP chain + pooling + final layer + L2 normalize
// f held as 48 packed f32x2 accumulators from birth -> no fp[48] repack,
// peak live regs ~150 (was ~250+ -> spilled to local).
// ---------------------------------------------------------------------------
struct __align__(16) SmemMLP {
    float2 pts[NPTS];          // 32KB
    float w1[32];              // [8][4]
    float w2[64];              // [8][8]
    float w3[128];             // [16][8]
    float w4[1024];            // [64][16]
    float w5[9216];            // [96][96]
    float mw[64];              // [4][16]
    float mb[4];
    float s1[8],  b1[8];
    float s2[8],  b2[8];
    float s3[16], b3[16];
    float s4[64], b4[64];
    float s5[96], b5[96];
};

extern "C" __global__ void __launch_bounds__(128, 2)
mlp_kernel(const float* __restrict__ x,
           const float* __restrict__ w1, const float* __restrict__ w2,
           const float* __restrict__ w3, const float* __restrict__ w4,
           const float* __restrict__ w5,
           const float* __restrict__ mw, const float* __restrict__ mb,
           const float* __restrict__ bn1, const float* __restrict__ bn2,
           const float* __restrict__ bn3, const float* __restrict__ bn4,
           const float* __restrict__ bn5,
           float* __restrict__ out) {
    extern __shared__ __align__(16) char smem_raw[];
    SmemMLP* sm = (SmemMLP*)smem_raw;

    const int tid = threadIdx.x;
    const int b   = blockIdx.y;

    // cooperative loads
    for (int i = tid; i < NPTS; i += 128) sm->pts[i] = ((const float2*)x)[(size_t)b * NPTS + i];
    for (int i = tid; i < 32;   i += 128) sm->w1[i] = w1[i];
    for (int i = tid; i < 64;   i += 128) sm->w2[i] = w2[i];
    for (int i = tid; i < 128;  i += 128) sm->w3[i] = w3[i];
    for (int i = tid; i < 1024; i += 128) sm->w4[i] = w4[i];
    for (int i = tid; i < 9216; i += 128) sm->w5[i] = w5[i];
    for (int i = tid; i < 64;   i += 128) sm->mw[i] = mw[i];
    if (tid < 4) sm->mb[tid] = mb[tid];
    // fold BN: scale = gamma*rsqrt(var+eps); bias = beta - mean*scale
    for (int i = tid; i < 8;  i += 128) {
        float s = bn1[i] * rsqrtf(bn1[24 + i] + 1e-5f);
        sm->s1[i] = s; sm->b1[i] = bn1[8 + i] - bn1[16 + i] * s;
        float t = bn2[i] * rsqrtf(bn2[24 + i] + 1e-5f);
        sm->s2[i] = t; sm->b2[i] = bn2[8 + i] - bn2[16 + i] * t;
    }
    for (int i = tid; i < 16; i += 128) {
        float s = bn3[i] * rsqrtf(bn3[48 + i] + 1e-5f);
        sm->s3[i] = s; sm->b3[i] = bn3[16 + i] - bn3[32 + i] * s;
    }
    for (int i = tid; i < 64; i += 128) {
        float s = bn4[i] * rsqrtf(bn4[192 + i] + 1e-5f);
        sm->s4[i] = s; sm->b4[i] = bn4[64 + i] - bn4[128 + i] * s;
    }
    for (int i = tid; i < 96; i += 128) {
        float s = bn5[i] * rsqrtf(bn5[288 + i] + 1e-5f);
        sm->s5[i] = s; sm->b5[i] = bn5[96 + i] - bn5[192 + i] * s;
    }
    __syncthreads();

    const int n  = blockIdx.x * 128 + tid;
    const int gq = b * NPTS + n;
    const int* __restrict__ gi = g_idx + (size_t)gq * KNN_K;

    // packed f32x2 pooled-feature accumulators: f[i] holds features (2i, 2i+1)
    unsigned long long f[48];
#pragma unroll
    for (int i = 0; i < 48; ++i) f[i] = 0ULL;

    const float2 ctr = sm->pts[n];

#pragma unroll 1
    for (int k = 0; k < KNN_K; ++k) {
        const int nbk = gi[k];
        const float2 P = sm->pts[nbk];
        const unsigned long long m1p = pack2(sm->mw[k],      sm->mw[k]);
        const unsigned long long m2p = pack2(sm->mw[16 + k], sm->mw[16 + k]);
        const unsigned long long m3p = pack2(sm->mw[32 + k], sm->mw[32 + k]);
        const unsigned long long m4p = pack2(sm->mw[48 + k], sm->mw[48 + k]);

        // layer 1: 4 -> 8
        float h1[8];
#pragma unroll
        for (int o = 0; o < 8; o += 2) {
#pragma unroll
            for (int t = 0; t < 2; ++t) {
                float4 w = *(const float4*)(sm->w1 + (o + t) * 4);
                float v = P.x * w.x + P.y * w.y + ctr.x * w.z + ctr.y * w.w;
                h1[o + t] = fmaxf(fmaf(v, sm->s1[o + t], sm->b1[o + t]), 0.0f);
            }
            f[o / 2] = ffma2(pack2(h1[o], h1[o + 1]), m1p, f[o / 2]);
        }
        // layer 2: 8 -> 8
        float h2[8];
#pragma unroll
        for (int o = 0; o < 8; o += 2) {
#pragma unroll
            for (int t = 0; t < 2; ++t) {
                const float4* w = (const float4*)(sm->w2 + (o + t) * 8);
                float4 wa = w[0], wb = w[1];
                float v = h1[0] * wa.x + h1[1] * wa.y + h1[2] * wa.z + h1[3] * wa.w
                        + h1[4] * wb.x + h1[5] * wb.y + h1[6] * wb.z + h1[7] * wb.w;
                h2[o + t] = fmaxf(fmaf(v, sm->s2[o + t], sm->b2[o + t]), 0.0f);
            }
            f[4 + o / 2] = ffma2(pack2(h2[o], h2[o + 1]), m2p, f[4 + o / 2]);
        }
        // layer 3: 8 -> 16, stored packed in pairs for layer-4 f32x2 dots
        unsigned long long h3p[8];
#pragma unroll
        for (int o = 0; o < 16; o += 2) {
            float vv[2];
#pragma unroll
            for (int t = 0; t < 2; ++t) {
                const float4* w = (const float4*)(sm->w3 + (o + t) * 8);
                float4 wa = w[0], wb = w[1];
                float v = h2[0] * wa.x + h2[1] * wa.y + h2[2] * wa.z + h2[3] * wa.w
                        + h2[4] * wb.x + h2[5] * wb.y + h2[6] * wb.z + h2[7] * wb.w;
                vv[t] = fmaxf(fmaf(v, sm->s3[o + t], sm->b3[o + t]), 0.0f);
            }
            h3p[o / 2] = pack2(vv[0], vv[1]);
            f[8 + o / 2] = ffma2(h3p[o / 2], m3p, f[8 + o / 2]);
        }
        // layer 4: 16 -> 64 (packed f32x2 dot16)
#pragma unroll
        for (int o = 0; o < 64; o += 2) {
            float vv[2];
#pragma unroll
            for (int t = 0; t < 2; ++t) {
                const ulonglong2* wrow = (const ulonglong2*)(sm->w4 + (o + t) * 16);
                ulonglong2 wa = wrow[0], wb = wrow[1], wc = wrow[2], wd = wrow[3];
                unsigned long long acc = ffma2(h3p[0], wa.x, 0ULL);
                acc = ffma2(h3p[1], wa.y, acc);
                acc = ffma2(h3p[2], wb.x, acc);
                acc = ffma2(h3p[3], wb.y, acc);
                acc = ffma2(h3p[4], wc.x, acc);
                acc = ffma2(h3p[5], wc.y, acc);
                acc = ffma2(h3p[6], wd.x, acc);
                acc = ffma2(h3p[7], wd.y, acc);
                float lo, hi; unpack2(acc, lo, hi);
                float v = lo + hi;
                vv[t] = fmaxf(fmaf(v, sm->s4[o + t], sm->b4[o + t]), 0.0f);
            }
            f[16 + o / 2] = ffma2(pack2(vv[0], vv[1]), m4p, f[16 + o / 2]);
        }
    }

    // mlp biases (per segment scalar, pair-aligned segments)
    {
        const unsigned long long c0 = pack2(sm->mb[0], sm->mb[0]);
        const unsigned long long c1 = pack2(sm->mb[1], sm->mb[1]);
        const unsigned long long c2 = pack2(sm->mb[2], sm->mb[2]);
        const unsigned long long c3 = pack2(sm->mb[3], sm->mb[3]);
#pragma unroll
        for (int i = 0; i < 4; ++i)  f[i]      = add2(f[i], c0);
#pragma unroll
        for (int i = 0; i < 4; ++i)  f[4 + i]  = add2(f[4 + i], c1);
#pragma unroll
        for (int i = 0; i < 8; ++i)  f[8 + i]  = add2(f[8 + i], c2);
#pragma unroll
        for (int i = 0; i < 32; ++i) f[16 + i] = add2(f[16 + i], c3);
    }

    float* __restrict__ outp = out + (size_t)gq * 96;
    float ss = 0.0f;
#pragma unroll 2
    for (int o = 0; o < 96; ++o) {
        const ulonglong2* w = (const ulonglong2*)(sm->w5 + o * 96);
        unsigned long long acc = 0ULL;
#pragma unroll
        for (int j = 0; j < 24; ++j) {
            ulonglong2 ww = w[j];
            acc = ffma2(f[2 * j],     ww.x, acc);
            acc = ffma2(f[2 * j + 1], ww.y, acc);
        }
        float lo, hi; unpack2(acc, lo, hi);
        float v = lo + hi;
        v = fmaxf(fmaf(v, sm->s5[o], sm->b5[o]), 0.0f);
        ss = fmaf(v, v, ss);
        outp[o] = v;
    }

    const float rn = rsqrtf(ss);
    float4* o4 = (float4*)outp;
#pragma unroll 4
    for (int i = 0; i < 24; ++i) {
        float4 v = o4[i];
        v.x *= rn; v.y *= rn; v.z *= rn; v.w *= rn;
        o4[i] = v;
    }
}

// ---------------------------------------------------------------------------
// launch
// ---------------------------------------------------------------------------
extern "C" void kernel_launch(void* const* d_in, const int* in_sizes, int n_in,
                              void* d_out, int out_size) {
    const float* x   = (const float*)d_in[0];
    const float* w1  = (const float*)d_in[1];
    const float* w2  = (const float*)d_in[2];
    const float* w3  = (const float*)d_in[3];
    const float* w4  = (const float*)d_in[4];
    const float* w5  = (const float*)d_in[5];
    const float* mw  = (const float*)d_in[6];
    const float* mb  = (const float*)d_in[7];
    const float* bn1 = (const float*)d_in[8];
    const float* bn2 = (const float*)d_in[9];
    const float* bn3 = (const float*)d_in[10];
    const float* bn4 = (const float*)d_in[11];
    const float* bn5 = (const float*)d_in[12];

    const size_t knn_smem = NPTS * sizeof(float4);   // 64KB
    const size_t mlp_smem = sizeof(SmemMLP);         // ~75KB

    cudaFuncSetAttribute(knn_kernel, cudaFuncAttributeMaxDynamicSharedMemorySize, (int)knn_smem);
    cudaFuncSetAttribute(mlp_kernel, cudaFuncAttributeMaxDynamicSharedMemorySize, (int)mlp_smem);

    dim3 grid(NPTS / 128, BATCH);
    knn_kernel<<<grid, 128, knn_smem>>>(x);
    mlp_kernel<<<grid, 128, mlp_smem>>>(x, w1, w2, w3, w4, w5, mw, mb,
                                        bn1, bn2, bn3, bn4, bn5, (float*)d_out);
}

// round 3
// speedup vs baseline: 4.6980x; 1.6462x over previous
#include <cuda_runtime.h>
#include <cstdint>

#define NPTS  4096
#define BATCH 8
#define KNN_K 16

// scratch for neighbor indices (within-batch indices), 8*4096*16 ints = 2MB
__device__ int g_idx[BATCH * NPTS * KNN_K];

// ---------------------------------------------------------------------------
// packed f32x2 helpers
// ---------------------------------------------------------------------------
__device__ __forceinline__ unsigned long long ffma2(unsigned long long a,
                                                    unsigned long long b,
                                                    unsigned long long c) {
    unsigned long long d;
    asm("fma.rn.f32x2 %0, %1, %2, %3;" : "=l"(d) : "l"(a), "l"(b), "l"(c));
    return d;
}
__device__ __forceinline__ unsigned long long add2(unsigned long long a,
                                                   unsigned long long b) {
    unsigned long long d;
    asm("add.rn.f32x2 %0, %1, %2;" : "=l"(d) : "l"(a), "l"(b));
    return d;
}
__device__ __forceinline__ unsigned long long pack2(float lo, float hi) {
    unsigned long long p;
    asm("mov.b64 %0, {%1, %2};" : "=l"(p) : "f"(lo), "f"(hi));
    return p;
}
__device__ __forceinline__ void unpack2(unsigned long long p, float& lo, float& hi) {
    asm("mov.b64 {%0, %1}, %2;" : "=f"(lo), "=f"(hi) : "l"(p));
}

// ---------------------------------------------------------------------------
// Kernel 1: brute-force exact KNN (top-16 by dist = sq[n]+sq[m]-2*dot, ties by idx)
// (byte-identical to round 1/2 — next optimization target)
// ---------------------------------------------------------------------------
extern "C" __global__ void __launch_bounds__(128)
knn_kernel(const float* __restrict__ x) {
    extern __shared__ __align__(16) char smem_raw[];
    float4* pts = (float4*)smem_raw;   // x, y, sq, pad : 64KB

    const int tid = threadIdx.x;
    const int b   = blockIdx.y;
    const float2* __restrict__ xb = ((const float2*)x) + (size_t)b * NPTS;

    for (int i = tid; i < NPTS; i += 128) {
        float2 v = xb[i];
        float sq = __fadd_rn(__fmul_rn(v.x, v.x), __fmul_rn(v.y, v.y));
        pts[i] = make_float4(v.x, v.y, sq, 0.0f);
    }
    __syncthreads();

    const int q = blockIdx.x * 128 + tid;
    const float4 qp = pts[q];
    const float qx = qp.x, qy = qp.y, qsq = qp.z;

    // sorted top-16: bu ascending (monotone-mapped distance bits), bi = index
    unsigned bu[KNN_K];
    int      bi[KNN_K];
#pragma unroll
    for (int s = 0; s < KNN_K; ++s) { bu[s] = 0xFFFFFFFFu; bi[s] = 0; }

#pragma unroll 4
    for (int j = 0; j < NPTS; ++j) {
        float4 p = pts[j];
        // exact reference formula, no FMA contraction
        float dot = __fadd_rn(__fmul_rn(qx, p.x), __fmul_rn(qy, p.y));
        float d   = __fsub_rn(__fadd_rn(qsq, p.z), __fmul_rn(2.0f, dot));
        int ib = __float_as_int(d);
        unsigned u = (ib >= 0) ? ((unsigned)ib ^ 0x80000000u) : ~(unsigned)ib;
        if (u < bu[KNN_K - 1]) {
            bool c[KNN_K];
#pragma unroll
            for (int s = 0; s < KNN_K; ++s) c[s] = (u < bu[s]);
#pragma unroll
            for (int s = KNN_K - 1; s >= 1; --s) {
                bu[s] = c[s - 1] ? bu[s - 1] : (c[s] ? u : bu[s]);
                bi[s] = c[s - 1] ? bi[s - 1] : (c[s] ? j : bi[s]);
            }
            if (c[0]) { bu[0] = u; bi[0] = j; }
        }
    }

    int* out = g_idx + ((size_t)b * NPTS + q) * KNN_K;
#pragma unroll
    for (int s = 0; s < KNN_K; ++s) out[s] = bi[s];
}

// ---------------------------------------------------------------------------
// Kernel 2: fused MLP chain + pooling + final layer + L2 normalize
// Packed-f in registers; unrolls CAPPED so ptxas can't front-batch smem loads
// past the register budget (that batching caused the round-2 spill).
// ---------------------------------------------------------------------------
struct __align__(16) SmemMLP {
    float2 pts[NPTS];          // 32KB
    float w1[32];              // [8][4]
    float w2[64];              // [8][8]
    float w3[128];             // [16][8]
    float w4[1024];            // [64][16]
    float w5[9216];            // [96][96]
    float mw[64];              // [4][16]
    float mb[4];
    float s1[8],  b1[8];
    float s2[8],  b2[8];
    float s3[16], b3[16];
    float s4[64], b4[64];
    float s5[96], b5[96];
};

extern "C" __global__ void __launch_bounds__(128)
mlp_kernel(const float* __restrict__ x,
           const float* __restrict__ w1, const float* __restrict__ w2,
           const float* __restrict__ w3, const float* __restrict__ w4,
           const float* __restrict__ w5,
           const float* __restrict__ mw, const float* __restrict__ mb,
           const float* __restrict__ bn1, const float* __restrict__ bn2,
           const float* __restrict__ bn3, const float* __restrict__ bn4,
           const float* __restrict__ bn5,
           float* __restrict__ out) {
    extern __shared__ __align__(16) char smem_raw[];
    SmemMLP* sm = (SmemMLP*)smem_raw;

    const int tid = threadIdx.x;
    const int b   = blockIdx.y;

    // cooperative loads
    for (int i = tid; i < NPTS; i += 128) sm->pts[i] = ((const float2*)x)[(size_t)b * NPTS + i];
    for (int i = tid; i < 32;   i += 128) sm->w1[i] = w1[i];
    for (int i = tid; i < 64;   i += 128) sm->w2[i] = w2[i];
    for (int i = tid; i < 128;  i += 128) sm->w3[i] = w3[i];
    for (int i = tid; i < 1024; i += 128) sm->w4[i] = w4[i];
    for (int i = tid; i < 9216; i += 128) sm->w5[i] = w5[i];
    for (int i = tid; i < 64;   i += 128) sm->mw[i] = mw[i];
    if (tid < 4) sm->mb[tid] = mb[tid];
    // fold BN: scale = gamma*rsqrt(var+eps); bias = beta - mean*scale
    for (int i = tid; i < 8;  i += 128) {
        float s = bn1[i] * rsqrtf(bn1[24 + i] + 1e-5f);
        sm->s1[i] = s; sm->b1[i] = bn1[8 + i] - bn1[16 + i] * s;
        float t = bn2[i] * rsqrtf(bn2[24 + i] + 1e-5f);
        sm->s2[i] = t; sm->b2[i] = bn2[8 + i] - bn2[16 + i] * t;
    }
    for (int i = tid; i < 16; i += 128) {
        float s = bn3[i] * rsqrtf(bn3[48 + i] + 1e-5f);
        sm->s3[i] = s; sm->b3[i] = bn3[16 + i] - bn3[32 + i] * s;
    }
    for (int i = tid; i < 64; i += 128) {
        float s = bn4[i] * rsqrtf(bn4[192 + i] + 1e-5f);
        sm->s4[i] = s; sm->b4[i] = bn4[64 + i] - bn4[128 + i] * s;
    }
    for (int i = tid; i < 96; i += 128) {
        float s = bn5[i] * rsqrtf(bn5[288 + i] + 1e-5f);
        sm->s5[i] = s; sm->b5[i] = bn5[96 + i] - bn5[192 + i] * s;
    }
    __syncthreads();

    const int n  = blockIdx.x * 128 + tid;
    const int gq = b * NPTS + n;
    const int* __restrict__ gi = g_idx + (size_t)gq * KNN_K;

    // packed f32x2 pooled-feature accumulators: f[i] holds features (2i, 2i+1)
    unsigned long long f[48];
#pragma unroll
    for (int i = 0; i < 48; ++i) f[i] = 0ULL;

    const float2 ctr = sm->pts[n];

#pragma unroll 1
    for (int k = 0; k < KNN_K; ++k) {
        const int nbk = gi[k];
        const float2 P = sm->pts[nbk];
        const unsigned long long m1p = pack2(sm->mw[k],      sm->mw[k]);
        const unsigned long long m2p = pack2(sm->mw[16 + k], sm->mw[16 + k]);
        const unsigned long long m3p = pack2(sm->mw[32 + k], sm->mw[32 + k]);
        const unsigned long long m4p = pack2(sm->mw[48 + k], sm->mw[48 + k]);

        // layer 1: 4 -> 8
        float h1[8];
#pragma unroll
        for (int o = 0; o < 8; o += 2) {
#pragma unroll
            for (int t = 0; t < 2; ++t) {
                float4 w = *(const float4*)(sm->w1 + (o + t) * 4);
                float v = P.x * w.x + P.y * w.y + ctr.x * w.z + ctr.y * w.w;
                h1[o + t] = fmaxf(fmaf(v, sm->s1[o + t], sm->b1[o + t]), 0.0f);
            }
            f[o / 2] = ffma2(pack2(h1[o], h1[o + 1]), m1p, f[o / 2]);
        }
        // layer 2: 8 -> 8
        float h2[8];
#pragma unroll
        for (int o = 0; o < 8; o += 2) {
#pragma unroll
            for (int t = 0; t < 2; ++t) {
                const float4* w = (const float4*)(sm->w2 + (o + t) * 8);
                float4 wa = w[0], wb = w[1];
                float v = h1[0] * wa.x + h1[1] * wa.y + h1[2] * wa.z + h1[3] * wa.w
                        + h1[4] * wb.x + h1[5] * wb.y + h1[6] * wb.z + h1[7] * wb.w;
                h2[o + t] = fmaxf(fmaf(v, sm->s2[o + t], sm->b2[o + t]), 0.0f);
            }
            f[4 + o / 2] = ffma2(pack2(h2[o], h2[o + 1]), m2p, f[4 + o / 2]);
        }
        // layer 3: 8 -> 16, stored packed in pairs for layer-4 f32x2 dots
        unsigned long long h3p[8];
#pragma unroll
        for (int o = 0; o < 16; o += 2) {
            float vv[2];
#pragma unroll
            for (int t = 0; t < 2; ++t) {
                const float4* w = (const float4*)(sm->w3 + (o + t) * 8);
                float4 wa = w[0], wb = w[1];
                float v = h2[0] * wa.x + h2[1] * wa.y + h2[2] * wa.z + h2[3] * wa.w
                        + h2[4] * wb.x + h2[5] * wb.y + h2[6] * wb.z + h2[7] * wb.w;
                vv[t] = fmaxf(fmaf(v, sm->s3[o + t], sm->b3[o + t]), 0.0f);
            }
            h3p[o / 2] = pack2(vv[0], vv[1]);
            f[8 + o / 2] = ffma2(h3p[o / 2], m3p, f[8 + o / 2]);
        }
        // layer 4: 16 -> 64 (packed f32x2 dot16)
        // unroll 1: only 8 LDS.128 of weight data live per body -> no reg blowup
#pragma unroll 1
        for (int o = 0; o < 64; o += 2) {
            float vv[2];
#pragma unroll
            for (int t = 0; t < 2; ++t) {
                const ulonglong2* wrow = (const ulonglong2*)(sm->w4 + (o + t) * 16);
                ulonglong2 wa = wrow[0], wb = wrow[1], wc = wrow[2], wd = wrow[3];
                unsigned long long acc = ffma2(h3p[0], wa.x, 0ULL);
                acc = ffma2(h3p[1], wa.y, acc);
                acc = ffma2(h3p[2], wb.x, acc);
                acc = ffma2(h3p[3], wb.y, acc);
                acc = ffma2(h3p[4], wc.x, acc);
                acc = ffma2(h3p[5], wc.y, acc);
                acc = ffma2(h3p[6], wd.x, acc);
                acc = ffma2(h3p[7], wd.y, acc);
                float lo, hi; unpack2(acc, lo, hi);
                float v = lo + hi;
                vv[t] = fmaxf(fmaf(v, sm->s4[o + t], sm->b4[o + t]), 0.0f);
            }
            f[16 + o / 2] = ffma2(pack2(vv[0], vv[1]), m4p, f[16 + o / 2]);
        }
    }

    // mlp biases (per segment scalar, pair-aligned segments)
    {
        const unsigned long long c0 = pack2(sm->mb[0], sm->mb[0]);
        const unsigned long long c1 = pack2(sm->mb[1], sm->mb[1]);
        const unsigned long long c2 = pack2(sm->mb[2], sm->mb[2]);
        const unsigned long long c3 = pack2(sm->mb[3], sm->mb[3]);
#pragma unroll
        for (int i = 0; i < 4; ++i)  f[i]      = add2(f[i], c0);
#pragma unroll
        for (int i = 0; i < 4; ++i)  f[4 + i]  = add2(f[4 + i], c1);
#pragma unroll
        for (int i = 0; i < 8; ++i)  f[8 + i]  = add2(f[8 + i], c2);
#pragma unroll
        for (int i = 0; i < 32; ++i) f[16 + i] = add2(f[16 + i], c3);
    }

    // final 96x96 layer: 2 outputs per body, 2 accumulator chains each
    // (4 independent ffma2 chains for ILP), inner unroll capped at 6
    // -> at most 12 LDS.128 of w5 batched (48 regs) on top of f (96 regs).
    float* __restrict__ outp = out + (size_t)gq * 96;
    float ss = 0.0f;
#pragma unroll 1
    for (int o = 0; o < 96; o += 2) {
        const ulonglong2* wA = (const ulonglong2*)(sm->w5 + o * 96);
        const ulonglong2* wB = (const ulonglong2*)(sm->w5 + (o + 1) * 96);
        unsigned long long a0 = 0ULL, a1 = 0ULL, b0 = 0ULL, b1 = 0ULL;
#pragma unroll 6
        for (int j = 0; j < 24; ++j) {
            ulonglong2 wa = wA[j];
            ulonglong2 wb = wB[j];
            a0 = ffma2(f[2 * j],     wa.x, a0);
            a1 = ffma2(f[2 * j + 1], wa.y, a1);
            b0 = ffma2(f[2 * j],     wb.x, b0);
            b1 = ffma2(f[2 * j + 1], wb.y, b1);
        }
        unsigned long long accA = add2(a0, a1);
        unsigned long long accB = add2(b0, b1);
        float lo, hi;
        unpack2(accA, lo, hi);
        float vA = lo + hi;
        unpack2(accB, lo, hi);
        float vB = lo + hi;
        vA = fmaxf(fmaf(vA, sm->s5[o],     sm->b5[o]),     0.0f);
        vB = fmaxf(fmaf(vB, sm->s5[o + 1], sm->b5[o + 1]), 0.0f);
        ss = fmaf(vA, vA, ss);
        ss = fmaf(vB, vB, ss);
        outp[o]     = vA;
        outp[o + 1] = vB;
    }

    const float rn = rsqrtf(ss);
    float4* o4 = (float4*)outp;
#pragma unroll 4
    for (int i = 0; i < 24; ++i) {
        float4 v = o4[i];
        v.x *= rn; v.y *= rn; v.z *= rn; v.w *= rn;
        o4[i] = v;
    }
}

// ---------------------------------------------------------------------------
// launch
// ---------------------------------------------------------------------------
extern "C" void kernel_launch(void* const* d_in, const int* in_sizes, int n_in,
                              void* d_out, int out_size) {
    const float* x   = (const float*)d_in[0];
    const float* w1  = (const float*)d_in[1];
    const float* w2  = (const float*)d_in[2];
    const float* w3  = (const float*)d_in[3];
    const float* w4  = (const float*)d_in[4];
    const float* w5  = (const float*)d_in[5];
    const float* mw  = (const float*)d_in[6];
    const float* mb  = (const float*)d_in[7];
    const float* bn1 = (const float*)d_in[8];
    const float* bn2 = (const float*)d_in[9];
    const float* bn3 = (const float*)d_in[10];
    const float* bn4 = (const float*)d_in[11];
    const float* bn5 = (const float*)d_in[12];

    const size_t knn_smem = NPTS * sizeof(float4);   // 64KB
    const size_t mlp_smem = sizeof(SmemMLP);         // ~75KB

    cudaFuncSetAttribute(knn_kernel, cudaFuncAttributeMaxDynamicSharedMemorySize, (int)knn_smem);
    cudaFuncSetAttribute(mlp_kernel, cudaFuncAttributeMaxDynamicSharedMemorySize, (int)mlp_smem);

    dim3 grid(NPTS / 128, BATCH);
    knn_kernel<<<grid, 128, knn_smem>>>(x);
    mlp_kernel<<<grid, 128, mlp_smem>>>(x, w1, w2, w3, w4, w5, mw, mb,
                                        bn1, bn2, bn3, bn4, bn5, (float*)d_out);
}